// round 4
// baseline (speedup 1.0000x reference)
#include <cuda_runtime.h>
#include <cstdint>

#define TT 1024
#define HH 50
#define PP 16
#define NB 4          // batches per CTA

// ---- packed f32x2 helpers ----
__device__ __forceinline__ uint64_t pack2(float lo, float hi) {
    uint64_t r; asm("mov.b64 %0, {%1, %2};" : "=l"(r) : "f"(lo), "f"(hi)); return r;
}
__device__ __forceinline__ void unpack2(uint64_t v, float& lo, float& hi) {
    asm("mov.b64 {%0, %1}, %2;" : "=f"(lo), "=f"(hi) : "l"(v));
}
__device__ __forceinline__ void fma2(uint64_t& a, uint64_t x, uint64_t y) {
    asm("fma.rn.f32x2 %0, %1, %2, %0;" : "+l"(a) : "l"(x), "l"(y));
}
__device__ __forceinline__ uint64_t add2(uint64_t a, uint64_t b) {
    uint64_t r; asm("add.rn.f32x2 %0, %1, %2;" : "=l"(r) : "l"(a), "l"(b)); return r;
}
__device__ __forceinline__ float tanh_hw(float v) {
    float r; asm("tanh.approx.f32 %0, %1;" : "=f"(r) : "f"(v)); return r;
}

__global__ __launch_bounds__(224, 2)
void lstm_fused_kernel(const float* __restrict__ x,
                       const float* __restrict__ params,
                       const float* __restrict__ W_ih,
                       const float* __restrict__ W_hh,
                       const float* __restrict__ b_ih,
                       const float* __restrict__ b_hh,
                       const float* __restrict__ W_lin,
                       const float* __restrict__ b_lin,
                       float* __restrict__ out)
{
    __shared__ __align__(16) float4 xs4[TT];          // x interleaved across 4 batches
    __shared__ __align__(16) float  hh[NB][32][52];   // per-batch h ring
    __shared__ __align__(16) float  wlin[68];         // W_lin padded

    const int tid  = threadIdx.x;
    const int lane = tid & 31;
    const int b0   = blockIdx.x * NB;

    // ---- init: interleave x rows, stage wlin, zero h[-1] ----
    {
        const float4* xr0 = reinterpret_cast<const float4*>(x + (size_t)(b0 + 0) * TT);
        const float4* xr1 = reinterpret_cast<const float4*>(x + (size_t)(b0 + 1) * TT);
        const float4* xr2 = reinterpret_cast<const float4*>(x + (size_t)(b0 + 2) * TT);
        const float4* xr3 = reinterpret_cast<const float4*>(x + (size_t)(b0 + 3) * TT);
        for (int i = tid; i < 256; i += 224) {        // 256 float4 chunks per row
            float4 a = xr0[i], b = xr1[i], c = xr2[i], d = xr3[i];
            xs4[4 * i + 0] = make_float4(a.x, b.x, c.x, d.x);
            xs4[4 * i + 1] = make_float4(a.y, b.y, c.y, d.y);
            xs4[4 * i + 2] = make_float4(a.z, b.z, c.z, d.z);
            xs4[4 * i + 3] = make_float4(a.w, b.w, c.w, d.w);
        }
        if (tid < 68) wlin[tid] = (tid < HH + PP) ? W_lin[tid] : 0.0f;
        if (tid < 52) {
            #pragma unroll
            for (int i = 0; i < NB; ++i) hh[i][31][tid] = 0.0f;
        }
    }
    const float blin = b_lin[0];

    // ---- gate mapping: thread 4j+k owns gate row r=k*50+j (200 real of 224) ----
    const bool real_gate = (tid < 4 * HH);
    const int  j = tid >> 2;
    const int  k = tid & 3;
    const int  r = k * HH + min(j, HH - 1);

    const float wih  = W_ih[r];
    const float bias = b_ih[r] + b_hh[r];
    uint64_t w2[25];
    {
        const float2* wr = reinterpret_cast<const float2*>(W_hh + r * HH);
        #pragma unroll
        for (int q = 0; q < 25; ++q) { float2 v = wr[q]; w2[q] = pack2(v.x, v.y); }
    }
    __syncthreads();

    // branchless activation coefs: k==2 -> tanh(g); else sigmoid via 0.5*tanh(0.5x)+0.5
    const float ascale = (k == 2) ? 1.0f : 0.5f;
    const float cm     = (k == 2) ? 1.0f : 0.5f;
    const float ca     = (k == 2) ? 0.0f : 0.5f;

    float c[NB];
    #pragma unroll
    for (int i = 0; i < NB; ++i) c[i] = 0.0f;

    #pragma unroll 1
    for (int t = 0; t < TT; ++t) {
        const int cur  = t & 31;
        const int prev = (t + 31) & 31;

        const float4 xv = xs4[t];                     // 1 LDS.128 broadcast
        const float xb[NB] = { xv.x, xv.y, xv.z, xv.w };

        // 4 independent gate dots, 2 f32x2 chains each
        uint64_t a0[NB], a1[NB];
        const ulonglong2* hp2[NB];
        const uint64_t*   hp1[NB];
        #pragma unroll
        for (int i = 0; i < NB; ++i) {
            a0[i] = pack2(fmaf(xb[i], wih, bias), 0.0f);
            a1[i] = 0ull;
            hp2[i] = reinterpret_cast<const ulonglong2*>(&hh[i][prev][0]);
            hp1[i] = reinterpret_cast<const uint64_t*>(&hh[i][prev][0]);
        }
        #pragma unroll
        for (int q = 0; q < 12; ++q) {                // pairs 0..23 (floats 0..47)
            #pragma unroll
            for (int i = 0; i < NB; ++i) {
                ulonglong2 hv = hp2[i][q];            // LDS.128 broadcast
                fma2(a0[i], w2[2 * q],     hv.x);
                fma2(a1[i], w2[2 * q + 1], hv.y);
            }
        }
        float v[NB];
        #pragma unroll
        for (int i = 0; i < NB; ++i) {
            fma2(a0[i], w2[24], hp1[i][24]);          // floats 48,49
            float lo, hi; unpack2(add2(a0[i], a1[i]), lo, hi);
            v[i] = fmaf(cm, tanh_hw(ascale * (lo + hi)), ca);
        }

        // quad exchange: leader gathers f,g,o per batch
        const int qb = lane & ~3;
        #pragma unroll
        for (int i = 0; i < NB; ++i) {
            const float vf = __shfl_sync(0xffffffffu, v[i], qb | 1);
            const float vg = __shfl_sync(0xffffffffu, v[i], qb | 2);
            const float vo = __shfl_sync(0xffffffffu, v[i], qb | 3);
            if (k == 0) {
                c[i] = fmaf(vf, c[i], v[i] * vg);
                const float hnew = vo * tanh_hw(c[i]);
                if (real_gate) hh[i][cur][j] = hnew;
            }
        }

        // ---- bulk output flush every 32 steps: 1 thread per (batch, timestep) ----
        if ((t & 31) == 31) {
            __syncthreads();                          // h writes -> flush reads
            if (tid < 32 * NB) {
                const int bq  = tid >> 5;
                const int ttl = tid & 31;
                const int tg  = t - 31 + ttl;
                float s = blin;
                const float4* hv4 = reinterpret_cast<const float4*>(&hh[bq][ttl][0]);
                const float4* wv4 = reinterpret_cast<const float4*>(wlin);
                #pragma unroll
                for (int q = 0; q < 12; ++q) {
                    float4 h4 = hv4[q]; float4 w4 = wv4[q];
                    s = fmaf(h4.x, w4.x, s); s = fmaf(h4.y, w4.y, s);
                    s = fmaf(h4.z, w4.z, s); s = fmaf(h4.w, w4.w, s);
                }
                s = fmaf(hh[bq][ttl][48], wlin[48], s);
                s = fmaf(hh[bq][ttl][49], wlin[49], s);
                const float* prow = params + ((size_t)(b0 + bq) * TT + tg) * PP;
                const float4* p4 = reinterpret_cast<const float4*>(prow);
                #pragma unroll
                for (int q = 0; q < 4; ++q) {
                    float4 p = p4[q];
                    s = fmaf(p.x, wlin[HH + 4 * q + 0], s);
                    s = fmaf(p.y, wlin[HH + 4 * q + 1], s);
                    s = fmaf(p.z, wlin[HH + 4 * q + 2], s);
                    s = fmaf(p.w, wlin[HH + 4 * q + 3], s);
                }
                out[(size_t)(b0 + bq) * TT + tg] = s;
            }
        }

        __syncthreads();                              // step barrier (h RAW + ring reuse)
    }
}

extern "C" void kernel_launch(void* const* d_in, const int* in_sizes, int n_in,
                              void* d_out, int out_size)
{
    const float* x      = (const float*)d_in[0];
    const float* params = (const float*)d_in[1];
    const float* W_ih   = (const float*)d_in[2];
    const float* W_hh   = (const float*)d_in[3];
    const float* b_ih   = (const float*)d_in[4];
    const float* b_hh   = (const float*)d_in[5];
    const float* W_lin  = (const float*)d_in[6];
    const float* b_lin  = (const float*)d_in[7];
    float* out = (float*)d_out;

    const int B = in_sizes[0] / TT;                   // 1024
    lstm_fused_kernel<<<B / NB, 224>>>(x, params, W_ih, W_hh, b_ih, b_hh,
                                       W_lin, b_lin, out);
}

// round 5
// speedup vs baseline: 1.3498x; 1.3498x over previous
#include <cuda_runtime.h>
#include <cuda_fp16.h>
#include <cstdint>

#define TT 1024
#define HH 50
#define PP 16

__device__ __forceinline__ float tanh_hw(float v) {
    float r; asm("tanh.approx.f32 %0, %1;" : "=f"(r) : "f"(v)); return r;
}
__device__ __forceinline__ __half2 as_h2(unsigned u) {
    return *reinterpret_cast<const __half2*>(&u);
}
__device__ __forceinline__ unsigned as_u32(__half2 h) {
    return *reinterpret_cast<const unsigned*>(&h);
}

__global__ __launch_bounds__(224, 4)
void lstm_fused_kernel(const float* __restrict__ x,
                       const float* __restrict__ params,
                       const float* __restrict__ W_ih,
                       const float* __restrict__ W_hh,
                       const float* __restrict__ b_ih,
                       const float* __restrict__ b_hh,
                       const float* __restrict__ W_lin,
                       const float* __restrict__ b_lin,
                       float* __restrict__ out)
{
    __shared__ __align__(16) float2 xs2[TT];          // (x_b0[t], x_b1[t])
    __shared__ __align__(16) __half hh16[2][32][64];  // fp16 h ring (dot operand), 128B rows
    __shared__ __align__(16) float  hh32[2][32][52];  // fp32 h ring (output head)
    __shared__ __align__(16) float  wlin[68];

    const int tid  = threadIdx.x;
    const int lane = tid & 31;
    const int b0   = blockIdx.x * 2;

    // ---- init ----
    {
        const float4* xr0 = reinterpret_cast<const float4*>(x + (size_t)b0 * TT);
        const float4* xr1 = reinterpret_cast<const float4*>(x + (size_t)(b0 + 1) * TT);
        for (int i = tid; i < 256; i += 224) {
            float4 a = xr0[i], b = xr1[i];
            xs2[4 * i + 0] = make_float2(a.x, b.x);
            xs2[4 * i + 1] = make_float2(a.y, b.y);
            xs2[4 * i + 2] = make_float2(a.z, b.z);
            xs2[4 * i + 3] = make_float2(a.w, b.w);
        }
        if (tid < 68) wlin[tid] = (tid < HH + PP) ? W_lin[tid] : 0.0f;
        // zero whole fp16 ring (pad columns must stay finite zero forever)
        uint32_t* z16 = reinterpret_cast<uint32_t*>(&hh16[0][0][0]);
        for (int i = tid; i < 2 * 32 * 64 / 2; i += 224) z16[i] = 0u;
        if (tid < 52) { hh32[0][31][tid] = 0.0f; hh32[1][31][tid] = 0.0f; }
    }
    const float blin = b_lin[0];

    // ---- gate mapping: thread 4j+k owns gate row r=k*50+j (200 real of 224) ----
    const bool real_gate = (tid < 4 * HH);
    const int  j = tid >> 2;
    const int  k = tid & 3;
    const int  r = k * HH + min(j, HH - 1);

    const float wih  = W_ih[r];
    const float bias = b_ih[r] + b_hh[r];
    __half2 w2h[28];                                  // 25 real pairs + 3 zero pads
    {
        const float2* wr = reinterpret_cast<const float2*>(W_hh + r * HH);
        #pragma unroll
        for (int q = 0; q < 25; ++q) { float2 v = wr[q]; w2h[q] = __floats2half2_rn(v.x, v.y); }
        #pragma unroll
        for (int q = 25; q < 28; ++q) w2h[q] = __floats2half2_rn(0.0f, 0.0f);
    }
    __syncthreads();

    // branchless activation coefs: k==2 -> tanh(g); else sigmoid via 0.5*tanh(0.5x)+0.5
    const float ascale = (k == 2) ? 1.0f : 0.5f;
    const float cm     = (k == 2) ? 1.0f : 0.5f;
    const float ca     = (k == 2) ? 0.0f : 0.5f;

    float c0 = 0.0f, c1 = 0.0f;

    #pragma unroll 1
    for (int t = 0; t < TT; ++t) {
        const int cur  = t & 31;
        const int prev = (t + 31) & 31;

        const float2 xv = xs2[t];                     // 1 LDS.64 broadcast
        const float g00 = fmaf(xv.x, wih, bias);
        const float g01 = fmaf(xv.y, wih, bias);

        // fp16 dual dot: 7 LDS.128 per batch, 2 HFMA2 chains each
        const uint4* hA = reinterpret_cast<const uint4*>(&hh16[0][prev][0]);
        const uint4* hB = reinterpret_cast<const uint4*>(&hh16[1][prev][0]);
        __half2 a0 = __floats2half2_rn(0.f, 0.f), a1 = a0, b0h = a0, b1h = a0;
        #pragma unroll
        for (int q = 0; q < 7; ++q) {
            uint4 va = hA[q];                         // 8 halfs (4 half2)
            uint4 vb = hB[q];
            a0  = __hfma2(w2h[4 * q + 0], as_h2(va.x), a0);
            a1  = __hfma2(w2h[4 * q + 1], as_h2(va.y), a1);
            a0  = __hfma2(w2h[4 * q + 2], as_h2(va.z), a0);
            a1  = __hfma2(w2h[4 * q + 3], as_h2(va.w), a1);
            b0h = __hfma2(w2h[4 * q + 0], as_h2(vb.x), b0h);
            b1h = __hfma2(w2h[4 * q + 1], as_h2(vb.y), b1h);
            b0h = __hfma2(w2h[4 * q + 2], as_h2(vb.z), b0h);
            b1h = __hfma2(w2h[4 * q + 3], as_h2(vb.w), b1h);
        }
        const __half2 sa = __hadd2(a0, a1);
        const __half2 sb = __hadd2(b0h, b1h);
        const float raw0 = g00 + __low2float(sa) + __high2float(sa);
        const float raw1 = g01 + __low2float(sb) + __high2float(sb);

        const float v0 = fmaf(cm, tanh_hw(ascale * raw0), ca);
        const float v1 = fmaf(cm, tanh_hw(ascale * raw1), ca);

        // pack both batches' gate value, 3 shfls to quad leader
        const unsigned pv = as_u32(__floats2half2_rn(v0, v1));
        const int qb = lane & ~3;
        const unsigned pf = __shfl_sync(0xffffffffu, pv, qb | 1);
        const unsigned pg = __shfl_sync(0xffffffffu, pv, qb | 2);
        const unsigned po = __shfl_sync(0xffffffffu, pv, qb | 3);

        if (k == 0) {
            const __half2 fh = as_h2(pf), gh = as_h2(pg), oh = as_h2(po);
            const float f0 = __low2float(fh), f1 = __high2float(fh);
            const float g0 = __low2float(gh), g1 = __high2float(gh);
            const float o0 = __low2float(oh), o1 = __high2float(oh);
            c0 = fmaf(f0, c0, v0 * g0);               // leader's own v stays fp32
            c1 = fmaf(f1, c1, v1 * g1);
            const float h0 = o0 * tanh_hw(c0);
            const float h1 = o1 * tanh_hw(c1);
            if (real_gate) {
                hh16[0][cur][j] = __float2half_rn(h0);
                hh16[1][cur][j] = __float2half_rn(h1);
                hh32[0][cur][j] = h0;
                hh32[1][cur][j] = h1;
            }
        }

        // ---- bulk output flush every 32 steps (exact fp32 path) ----
        if ((t & 31) == 31) {
            __syncthreads();
            if (tid < 64) {
                const int bq  = tid >> 5;
                const int ttl = tid & 31;
                const int tg  = t - 31 + ttl;
                float s = blin;
                const float4* hv4 = reinterpret_cast<const float4*>(&hh32[bq][ttl][0]);
                const float4* wv4 = reinterpret_cast<const float4*>(wlin);
                #pragma unroll
                for (int q = 0; q < 12; ++q) {
                    float4 h4 = hv4[q]; float4 w4 = wv4[q];
                    s = fmaf(h4.x, w4.x, s); s = fmaf(h4.y, w4.y, s);
                    s = fmaf(h4.z, w4.z, s); s = fmaf(h4.w, w4.w, s);
                }
                s = fmaf(hh32[bq][ttl][48], wlin[48], s);
                s = fmaf(hh32[bq][ttl][49], wlin[49], s);
                const float* prow = params + ((size_t)(b0 + bq) * TT + tg) * PP;
                const float4* p4 = reinterpret_cast<const float4*>(prow);
                #pragma unroll
                for (int q = 0; q < 4; ++q) {
                    float4 p = p4[q];
                    s = fmaf(p.x, wlin[HH + 4 * q + 0], s);
                    s = fmaf(p.y, wlin[HH + 4 * q + 1], s);
                    s = fmaf(p.z, wlin[HH + 4 * q + 2], s);
                    s = fmaf(p.w, wlin[HH + 4 * q + 3], s);
                }
                out[(size_t)(b0 + bq) * TT + tg] = s;
            }
        }

        __syncthreads();                              // step barrier
    }
}

extern "C" void kernel_launch(void* const* d_in, const int* in_sizes, int n_in,
                              void* d_out, int out_size)
{
    const float* x      = (const float*)d_in[0];
    const float* params = (const float*)d_in[1];
    const float* W_ih   = (const float*)d_in[2];
    const float* W_hh   = (const float*)d_in[3];
    const float* b_ih   = (const float*)d_in[4];
    const float* b_hh   = (const float*)d_in[5];
    const float* W_lin  = (const float*)d_in[6];
    const float* b_lin  = (const float*)d_in[7];
    float* out = (float*)d_out;

    const int B = in_sizes[0] / TT;                   // 1024
    lstm_fused_kernel<<<B / 2, 224>>>(x, params, W_ih, W_hh, b_ih, b_hh,
                                      W_lin, b_lin, out);
}

// round 6
// speedup vs baseline: 1.6071x; 1.1907x over previous
#include <cuda_runtime.h>
#include <cuda_fp16.h>
#include <cstdint>

#define TT 1024
#define HH 50
#define PP 16
#define NB 4
#define RSTRIDE 592   // ring slot stride (148 words, %32=20 -> spread flush banks)
#define BSTRIDE 144   // per-batch stride in slot (36 words -> conflict-free quad reads)

__device__ __forceinline__ float tanh_hw(float v) {
    float r; asm("tanh.approx.f32 %0, %1;" : "=f"(r) : "f"(v)); return r;
}
__device__ __forceinline__ __half2 as_h2(unsigned u) {
    return *reinterpret_cast<const __half2*>(&u);
}

__global__ __launch_bounds__(224, 2)
void lstm_fused_kernel(const float* __restrict__ x,
                       const float* __restrict__ params,
                       const float* __restrict__ W_ih,
                       const float* __restrict__ W_hh,
                       const float* __restrict__ b_ih,
                       const float* __restrict__ b_hh,
                       const float* __restrict__ W_lin,
                       const float* __restrict__ b_lin,
                       float* __restrict__ out)
{
    __shared__ __align__(16) float4 xs4[TT];                 // x interleaved over 4 batches
    __shared__ __align__(16) unsigned char ring[32 * RSTRIDE]; // fp16 h ring
    __shared__ float wlin[68];

    const int tid = threadIdx.x;
    const int b   = tid & 3;          // batch within CTA
    const int j   = tid >> 2;         // hidden unit 0..55 (>=50 are pads)
    const int jj  = min(j, HH - 1);
    const int b0  = blockIdx.x * NB;

    // ---- init: interleave x, zero ring, stage wlin ----
    {
        const float4* xr0 = reinterpret_cast<const float4*>(x + (size_t)(b0 + 0) * TT);
        const float4* xr1 = reinterpret_cast<const float4*>(x + (size_t)(b0 + 1) * TT);
        const float4* xr2 = reinterpret_cast<const float4*>(x + (size_t)(b0 + 2) * TT);
        const float4* xr3 = reinterpret_cast<const float4*>(x + (size_t)(b0 + 3) * TT);
        for (int i = tid; i < 256; i += 224) {
            float4 a = xr0[i], bb = xr1[i], cc = xr2[i], d = xr3[i];
            xs4[4 * i + 0] = make_float4(a.x, bb.x, cc.x, d.x);
            xs4[4 * i + 1] = make_float4(a.y, bb.y, cc.y, d.y);
            xs4[4 * i + 2] = make_float4(a.z, bb.z, cc.z, d.z);
            xs4[4 * i + 3] = make_float4(a.w, bb.w, cc.w, d.w);
        }
        uint32_t* rz = reinterpret_cast<uint32_t*>(ring);
        for (int i = tid; i < 32 * RSTRIDE / 4; i += 224) rz[i] = 0u;
        if (tid < 68) wlin[tid] = (tid < HH + PP) ? W_lin[tid] : 0.0f;
    }
    const float blin = b_lin[0];

    // ---- per-thread: all 4 gate rows for unit jj (i,f,g,o) ----
    __half2 w[4][25];
    float wih[4], bias[4];
    #pragma unroll
    for (int k = 0; k < 4; ++k) {
        const int r = k * HH + jj;
        wih[k]  = W_ih[r];
        bias[k] = b_ih[r] + b_hh[r];
        const float2* wr = reinterpret_cast<const float2*>(W_hh + r * HH);
        #pragma unroll
        for (int q = 0; q < 25; ++q) { float2 v = wr[q]; w[k][q] = __floats2half2_rn(v.x, v.y); }
    }
    __syncthreads();

    float c = 0.0f;

    #pragma unroll 1
    for (int t = 0; t < TT; ++t) {
        const int cur  = t & 31;
        const int prev = (t + 31) & 31;

        const unsigned char* hrow = ring + prev * RSTRIDE + b * BSTRIDE;
        uint4 hv[6];
        #pragma unroll
        for (int q = 0; q < 6; ++q) hv[q] = reinterpret_cast<const uint4*>(hrow)[q];
        const unsigned htail = reinterpret_cast<const unsigned*>(hrow)[24];  // h48,h49
        const float xv = reinterpret_cast<const float*>(&xs4[t])[b];          // LDS.32 (4-way bcast)

        float raw[4];
        #pragma unroll
        for (int k = 0; k < 4; ++k) {
            __half2 a0 = __floats2half2_rn(0.f, 0.f), a1 = a0;
            #pragma unroll
            for (int q = 0; q < 6; ++q) {
                a0 = __hfma2(w[k][4 * q + 0], as_h2(hv[q].x), a0);
                a1 = __hfma2(w[k][4 * q + 1], as_h2(hv[q].y), a1);
                a0 = __hfma2(w[k][4 * q + 2], as_h2(hv[q].z), a0);
                a1 = __hfma2(w[k][4 * q + 3], as_h2(hv[q].w), a1);
            }
            a0 = __hfma2(w[k][24], as_h2(htail), a0);
            const __half2 s = __hadd2(a0, a1);
            raw[k] = fmaf(xv, wih[k], bias[k]) + __low2float(s) + __high2float(s);
        }

        // gates: i,f,o sigmoid via tanh; g tanh — all thread-local, no shfl
        const float vi = fmaf(0.5f, tanh_hw(0.5f * raw[0]), 0.5f);
        const float vf = fmaf(0.5f, tanh_hw(0.5f * raw[1]), 0.5f);
        const float vg = tanh_hw(raw[2]);
        const float vo = fmaf(0.5f, tanh_hw(0.5f * raw[3]), 0.5f);

        c = fmaf(vf, c, vi * vg);
        const float h = vo * tanh_hw(c);
        if (j < HH)
            *reinterpret_cast<__half*>(ring + cur * RSTRIDE + b * BSTRIDE + 2 * j) =
                __float2half_rn(h);

        // ---- bulk output flush every 32 steps (reads fp16 h) ----
        if ((t & 31) == 31) {
            __syncthreads();
            if (tid < 128) {
                const int fb  = tid >> 5;
                const int ttl = tid & 31;
                const int tg  = t - 31 + ttl;
                const unsigned char* hr = ring + ttl * RSTRIDE + fb * BSTRIDE;
                float s = blin;
                #pragma unroll
                for (int q = 0; q < 6; ++q) {
                    uint4 v = reinterpret_cast<const uint4*>(hr)[q];
                    float2 f0 = __half22float2(as_h2(v.x));
                    float2 f1 = __half22float2(as_h2(v.y));
                    float2 f2 = __half22float2(as_h2(v.z));
                    float2 f3 = __half22float2(as_h2(v.w));
                    s = fmaf(f0.x, wlin[8 * q + 0], s); s = fmaf(f0.y, wlin[8 * q + 1], s);
                    s = fmaf(f1.x, wlin[8 * q + 2], s); s = fmaf(f1.y, wlin[8 * q + 3], s);
                    s = fmaf(f2.x, wlin[8 * q + 4], s); s = fmaf(f2.y, wlin[8 * q + 5], s);
                    s = fmaf(f3.x, wlin[8 * q + 6], s); s = fmaf(f3.y, wlin[8 * q + 7], s);
                }
                {
                    float2 ft = __half22float2(as_h2(reinterpret_cast<const unsigned*>(hr)[24]));
                    s = fmaf(ft.x, wlin[48], s); s = fmaf(ft.y, wlin[49], s);
                }
                const float* prow = params + ((size_t)(b0 + fb) * TT + tg) * PP;
                const float4* p4 = reinterpret_cast<const float4*>(prow);
                #pragma unroll
                for (int q = 0; q < 4; ++q) {
                    float4 p = p4[q];
                    s = fmaf(p.x, wlin[HH + 4 * q + 0], s);
                    s = fmaf(p.y, wlin[HH + 4 * q + 1], s);
                    s = fmaf(p.z, wlin[HH + 4 * q + 2], s);
                    s = fmaf(p.w, wlin[HH + 4 * q + 3], s);
                }
                out[(size_t)(b0 + fb) * TT + tg] = s;
            }
        }

        __syncthreads();   // step barrier: h RAW + ring-slot reuse
    }
}

extern "C" void kernel_launch(void* const* d_in, const int* in_sizes, int n_in,
                              void* d_out, int out_size)
{
    const float* x      = (const float*)d_in[0];
    const float* params = (const float*)d_in[1];
    const float* W_ih   = (const float*)d_in[2];
    const float* W_hh   = (const float*)d_in[3];
    const float* b_ih   = (const float*)d_in[4];
    const float* b_hh   = (const float*)d_in[5];
    const float* W_lin  = (const float*)d_in[6];
    const float* b_lin  = (const float*)d_in[7];
    float* out = (float*)d_out;

    const int B = in_sizes[0] / TT;                   // 1024
    lstm_fused_kernel<<<B / NB, 224>>>(x, params, W_ih, W_hh, b_ih, b_hh,
                                       W_lin, b_lin, out);
}